// round 15
// baseline (speedup 1.0000x reference)
#include <cuda_runtime.h>
#include <cuda_fp16.h>
#include <cstdint>

#define LAT   2048
#define MAXB  4096
#define K1PAD 2112            // n_freq (2074) padded to multiple of 64

// ---------------------------------------------------------------------------
// Scratch (static __device__ — no allocations allowed)
// ---------------------------------------------------------------------------
__device__ __half g_Wt[(size_t)LAT * K1PAD];   // W^T, K-major (K = n_freq)
__device__ __half g_Ct[(size_t)LAT * K1PAD];   // C^T, K-major
__device__ __half g_Mt[(size_t)LAT * LAT];     // M^T rows n, K-major over m
__device__ __half g_x [(size_t)MAXB * LAT];    // x, fp16
__device__ unsigned g_max_bits;
__device__ unsigned g_done;

// ---------------------------------------------------------------------------
// Helpers
// ---------------------------------------------------------------------------
__device__ __forceinline__ unsigned fenc(float f) {
    unsigned u = __float_as_uint(f);
    return (u & 0x80000000u) ? ~u : (u | 0x80000000u);
}
__device__ __forceinline__ float fdec(unsigned u) {
    unsigned b = (u & 0x80000000u) ? (u ^ 0x80000000u) : ~u;
    return __uint_as_float(b);
}
__device__ __forceinline__ uint32_t smem_u32(const void* p) {
    return (uint32_t)__cvta_generic_to_shared(p);
}
__device__ __forceinline__ void cpasync16(uint32_t dst, const void* src) {
    asm volatile("cp.async.cg.shared.global [%0], [%1], 16;" :: "r"(dst), "l"(src));
}
#define CP_COMMIT() asm volatile("cp.async.commit_group;" ::: "memory")
#define CP_WAIT1()  asm volatile("cp.async.wait_group 1;" ::: "memory")

__device__ __forceinline__ void ldsm4(uint32_t* r, uint32_t addr) {
    asm volatile("ldmatrix.sync.aligned.m8n8.x4.shared.b16 {%0,%1,%2,%3}, [%4];"
                 : "=r"(r[0]), "=r"(r[1]), "=r"(r[2]), "=r"(r[3]) : "r"(addr));
}
__device__ __forceinline__ void mma16816(float* c, const uint32_t* a, const uint32_t* b) {
    asm volatile("mma.sync.aligned.m16n8k16.row.col.f32.f16.f16.f32 "
                 "{%0,%1,%2,%3}, {%4,%5,%6,%7}, {%8,%9}, {%0,%1,%2,%3};"
                 : "+f"(c[0]), "+f"(c[1]), "+f"(c[2]), "+f"(c[3])
                 : "r"(a[0]), "r"(a[1]), "r"(a[2]), "r"(a[3]), "r"(b[0]), "r"(b[1]));
}

// smem tile geometry: 128 rows x 64 fp16 (128B) padded to 144B (9*16B,
// conflict-free for ldmatrix)
#define ROWB        144
#define TILE_B      (128 * ROWB)      // 18432
#define STAGE_B     (2 * TILE_B)      // 36864 (A, B)
#define NSTAGE      3
#define SMEM_BYTES  (NSTAGE * STAGE_B)   // 110592 -> occ=1

// ---------------------------------------------------------------------------
// Fused prep kernel: transpose W -> g_Wt, transpose C -> g_Ct, convert x -> g_x.
// 1-D grid of 256-thread blocks; also resets g_max_bits / g_done.
// ---------------------------------------------------------------------------
#define TRANS_BX (LAT / 32)                 // 64
#define TRANS_BY (K1PAD / 32)               // 66
#define TRANS_BLOCKS (TRANS_BX * TRANS_BY)  // 4224 per tensor
__global__ void prep_kernel(const float* __restrict__ x,
                            const float* __restrict__ W,
                            const float* __restrict__ C, int K, int n2)
{
    __shared__ float t[32][33];
    const int b = blockIdx.x;
    const int tid = threadIdx.x;
    if (b == 0 && tid == 0) { g_max_bits = 0u; g_done = 0u; }

    if (b < 2 * TRANS_BLOCKS) {
        const int which = (b >= TRANS_BLOCKS) ? 1 : 0;
        const int bb = which ? b - TRANS_BLOCKS : b;
        const float* src = which ? C : W;
        __half* dst = which ? g_Ct : g_Wt;
        const int mb = (bb % TRANS_BX) * 32;
        const int kb = (bb / TRANS_BX) * 32;
        const int tx = tid & 31, ty = tid >> 5;
#pragma unroll
        for (int r = ty; r < 32; r += 8) {
            const int k = kb + r;
            t[r][tx] = (k < K) ? src[(size_t)k * LAT + mb + tx] : 0.f;
        }
        __syncthreads();
#pragma unroll
        for (int r = ty; r < 32; r += 8)
            dst[(size_t)(mb + r) * K1PAD + kb + tx] = __float2half_rn(t[tx][r]);
    } else {
        const int i = (b - 2 * TRANS_BLOCKS) * 256 + tid;
        if (i < n2) {
            const float2 v = ((const float2*)x)[i];
            ((__half2*)g_x)[i] = __floats2half2_rn(v.x, v.y);
        }
    }
}

// ---------------------------------------------------------------------------
// GEMM mainloop: 128x128 CTA tile, 512 threads = 16 warps (4m x 4n, warp tile
// 32x32), K-chunks of 64 (4 k16-steps), 3-stage cp.async pipeline (prefetch 2).
// ---------------------------------------------------------------------------
__device__ __forceinline__ void gemm_main(
    const __half* __restrict__ A, const __half* __restrict__ B,
    int arow0, int brow0, int ldk, int nchunks,
    char* smem, float acc[2][4][4])
{
    const int tid = threadIdx.x;
    const int lane = tid & 31;
    const int w = tid >> 5;
    const int wm = w >> 2;
    const int wn = w & 3;
    const uint32_t sbase = smem_u32(smem);

#pragma unroll
    for (int mt = 0; mt < 2; mt++)
#pragma unroll
        for (int nj = 0; nj < 4; nj++)
#pragma unroll
            for (int q = 0; q < 4; q++) acc[mt][nj][q] = 0.f;

    const int lr = tid >> 2;
    const int lcB = (tid & 3) * 32;
    const __half* gA = A + (size_t)(arow0 + lr) * ldk + (lcB >> 1);
    const __half* gB = B + (size_t)(brow0 + lr) * ldk + (lcB >> 1);
    const uint32_t adst = sbase + lr * ROWB + lcB;
    const uint32_t bdst = sbase + TILE_B + lr * ROWB + lcB;

    uint32_t aoff[4][2], boff[4][2];
#pragma unroll
    for (int ks = 0; ks < 4; ks++) {
#pragma unroll
        for (int mt = 0; mt < 2; mt++)
            aoff[ks][mt] = sbase + (uint32_t)((wm * 32 + mt * 16 + (lane & 15)) * ROWB
                                              + ks * 32 + (lane >> 4) * 16);
#pragma unroll
        for (int nt = 0; nt < 2; nt++)
            boff[ks][nt] = sbase + (uint32_t)(TILE_B
                              + (wn * 32 + nt * 16 + (lane & 7) + (lane >> 4) * 8) * ROWB
                              + ks * 32 + ((lane >> 3) & 1) * 16);
    }

#define LOAD_STAGE(c, s)                                                       \
    do {                                                                       \
        const char* pa = (const char*)(gA + (size_t)(c) * 64);                 \
        const char* pb = (const char*)(gB + (size_t)(c) * 64);                 \
        const uint32_t so_ = (uint32_t)(s) * STAGE_B;                          \
        cpasync16(adst + so_,      pa);   cpasync16(adst + so_ + 16, pa + 16); \
        cpasync16(bdst + so_,      pb);   cpasync16(bdst + so_ + 16, pb + 16); \
    } while (0)

    LOAD_STAGE(0, 0); CP_COMMIT();
    LOAD_STAGE(1, 1); CP_COMMIT();

    int s = 0, ps = 2;
    for (int c = 0; c < nchunks; ++c) {
        CP_WAIT1();
        __syncthreads();
        if (c + 2 < nchunks) LOAD_STAGE(c + 2, ps);
        CP_COMMIT();

        const uint32_t so = (uint32_t)s * STAGE_B;
        uint32_t a[4][2][4], b[4][2][4];
#pragma unroll
        for (int ks = 0; ks < 4; ks++) {
            ldsm4(a[ks][0], aoff[ks][0] + so);
            ldsm4(a[ks][1], aoff[ks][1] + so);
            ldsm4(b[ks][0], boff[ks][0] + so);
            ldsm4(b[ks][1], boff[ks][1] + so);
        }
#pragma unroll
        for (int ks = 0; ks < 4; ks++)
#pragma unroll
            for (int mt = 0; mt < 2; mt++)
#pragma unroll
                for (int nt = 0; nt < 2; nt++) {
                    mma16816(acc[mt][nt * 2 + 0], a[ks][mt], &b[ks][nt][0]);
                    mma16816(acc[mt][nt * 2 + 1], a[ks][mt], &b[ks][nt][2]);
                }
        if (++s == NSTAGE) s = 0;
        if (++ps == NSTAGE) ps = 0;
    }
#undef LOAD_STAGE
}

// ---------------------------------------------------------------------------
// GEMM1: Mt[n][m] = sum_k Ct[n][k] * Wt[m][k]; epilogue rounds to fp16.
// ---------------------------------------------------------------------------
__global__ __launch_bounds__(512, 1) void gemm1_tc()
{
    extern __shared__ __align__(128) char smem[];
    float acc[2][4][4];
    gemm_main(g_Ct, g_Wt, blockIdx.y * 128, blockIdx.x * 128, K1PAD, K1PAD / 64,
              smem, acc);

    const int lane = threadIdx.x & 31;
    const int w = threadIdx.x >> 5;
    const int r0 = blockIdx.y * 128 + (w >> 2) * 32;
    const int c0 = blockIdx.x * 128 + (w & 3) * 32;

#pragma unroll
    for (int mt = 0; mt < 2; mt++) {
#pragma unroll
        for (int nj = 0; nj < 4; nj++) {
            const int col = c0 + nj * 8 + (lane & 3) * 2;
            const float* cc = acc[mt][nj];
#pragma unroll
            for (int h = 0; h < 2; h++) {
                const int r = r0 + mt * 16 + (lane >> 2) + h * 8;
                *(__half2*)(g_Mt + (size_t)r * LAT + col) =
                    __floats2half2_rn(cc[2 * h + 0], cc[2 * h + 1]);
            }
        }
    }
}

// ---------------------------------------------------------------------------
// GEMM2 (persistent, grid = 148, all CTAs resident): out = x @ M over 512
// tiles, fused global max, software grid barrier, fused rescale from L2.
// ---------------------------------------------------------------------------
#define G2_NT   (16 * (MAXB / 128))     // 512 tiles (16 n-tiles x 32 m-tiles)
__global__ __launch_bounds__(512, 1) void gemm2_tc(float* __restrict__ out)
{
    extern __shared__ __align__(128) char smem[];
    __shared__ float wmax[16];
    const int tid = threadIdx.x;
    const int lane = tid & 31;
    const int w = tid >> 5;

    for (int t = blockIdx.x; t < G2_NT; t += gridDim.x) {
        const int bx = t & 15;          // n tile
        const int by = t >> 4;          // m tile
        float acc[2][4][4];
        gemm_main(g_x, g_Mt, by * 128, bx * 128, LAT, LAT / 64, smem, acc);

        const int r0 = by * 128 + (w >> 2) * 32;
        const int c0 = bx * 128 + (w & 3) * 32;
        float lmax = -3.402823466e+38f;
#pragma unroll
        for (int mt = 0; mt < 2; mt++) {
#pragma unroll
            for (int nj = 0; nj < 4; nj++) {
                const int col = c0 + nj * 8 + (lane & 3) * 2;
                const float* cc = acc[mt][nj];
#pragma unroll
                for (int h = 0; h < 2; h++) {
                    const int r = r0 + mt * 16 + (lane >> 2) + h * 8;
                    float2 v = make_float2(cc[2 * h + 0], cc[2 * h + 1]);
                    lmax = fmaxf(lmax, fmaxf(v.x, v.y));
                    *(float2*)(out + (size_t)r * LAT + col) = v;
                }
            }
        }
#pragma unroll
        for (int o = 16; o > 0; o >>= 1)
            lmax = fmaxf(lmax, __shfl_xor_sync(0xFFFFFFFFu, lmax, o));
        if (lane == 0) wmax[w] = lmax;
        __syncthreads();
        if (tid == 0) {
            float m = wmax[0];
#pragma unroll
            for (int i = 1; i < 16; i++) m = fmaxf(m, wmax[i]);
            atomicMax(&g_max_bits, fenc(m));
        }
        __syncthreads();   // smem/wmax reuse protection for next tile
    }

    // ---- software grid barrier (all 148 CTAs are resident: grid <= SMs, occ=1)
    if (tid == 0) {
        __threadfence();
        atomicAdd(&g_done, 1u);
        while (atomicAdd(&g_done, 0u) < gridDim.x) { }
    }
    __syncthreads();

    // ---- fused rescale of this CTA's own tiles (L2-hot)
    const float inv = 1.0f / fdec(*(volatile unsigned*)&g_max_bits);
    const int rr = tid >> 2;              // 0..127
    const int cc0 = (tid & 3) * 32;       // 32 floats = 8 float4
    for (int t = blockIdx.x; t < G2_NT; t += gridDim.x) {
        const int bx = t & 15;
        const int by = t >> 4;
        float4* p = (float4*)(out + (size_t)(by * 128 + rr) * LAT + bx * 128 + cc0);
#pragma unroll
        for (int j = 0; j < 8; j++) {
            float4 v = p[j];
            v.x *= inv; v.y *= inv; v.z *= inv; v.w *= inv;
            p[j] = v;
        }
    }
}

// ---------------------------------------------------------------------------
extern "C" void kernel_launch(void* const* d_in, const int* in_sizes, int n_in,
                              void* d_out, int out_size)
{
    const float* x = (const float*)d_in[0];   // (B, 2048)
    const float* W = (const float*)d_in[1];   // (NF, 2048)
    const float* C = (const float*)d_in[2];   // (NF, 2048)
    float* out = (float*)d_out;

    const int B  = in_sizes[0] / LAT;         // 4096
    const int NF = in_sizes[1] / LAT;         // 2074

    cudaFuncSetAttribute(gemm1_tc, cudaFuncAttributeMaxDynamicSharedMemorySize, SMEM_BYTES);
    cudaFuncSetAttribute(gemm2_tc, cudaFuncAttributeMaxDynamicSharedMemorySize, SMEM_BYTES);

    // fused prep: transpose W, transpose C, convert x (+ reset max/done)
    const int n2 = B * LAT / 2;
    const int xblocks = (n2 + 255) / 256;
    prep_kernel<<<2 * TRANS_BLOCKS + xblocks, 256>>>(x, W, C, NF, n2);

    // GEMM1: Mt = (W^T C)^T — grid 16x16 = 256 CTAs, 512 threads, K-chunk 64
    gemm1_tc<<<dim3(LAT / 128, LAT / 128), 512, SMEM_BYTES>>>();

    // GEMM2 (persistent, 148 CTAs): out = x @ M + max + grid barrier + rescale
    gemm2_tc<<<148, 512, SMEM_BYTES>>>(out);
}

// round 16
// speedup vs baseline: 1.0280x; 1.0280x over previous
#include <cuda_runtime.h>
#include <cuda_fp16.h>
#include <cstdint>

#define LAT   2048
#define MAXB  4096
#define K1PAD 2112            // n_freq (2074) padded to multiple of 64

// ---------------------------------------------------------------------------
// Scratch (static __device__ — no allocations allowed)
// ---------------------------------------------------------------------------
__device__ __half g_Wt[(size_t)LAT * K1PAD];   // W^T, K-major (K = n_freq)
__device__ __half g_Ct[(size_t)LAT * K1PAD];   // C^T, K-major
__device__ __half g_Mt[(size_t)LAT * LAT];     // M^T rows n, K-major over m
__device__ __half g_x [(size_t)MAXB * LAT];    // x, fp16
__device__ unsigned g_max_bits;
__device__ unsigned g_tix;                     // global tile queue cursor
__device__ unsigned g_colcnt[16];              // gemm1 n-column completion

// ---------------------------------------------------------------------------
// Helpers
// ---------------------------------------------------------------------------
__device__ __forceinline__ unsigned fenc(float f) {
    unsigned u = __float_as_uint(f);
    return (u & 0x80000000u) ? ~u : (u | 0x80000000u);
}
__device__ __forceinline__ float fdec(unsigned u) {
    unsigned b = (u & 0x80000000u) ? (u ^ 0x80000000u) : ~u;
    return __uint_as_float(b);
}
__device__ __forceinline__ uint32_t smem_u32(const void* p) {
    return (uint32_t)__cvta_generic_to_shared(p);
}
__device__ __forceinline__ void cpasync16(uint32_t dst, const void* src) {
    asm volatile("cp.async.cg.shared.global [%0], [%1], 16;" :: "r"(dst), "l"(src));
}
#define CP_COMMIT() asm volatile("cp.async.commit_group;" ::: "memory")
#define CP_WAIT1()  asm volatile("cp.async.wait_group 1;" ::: "memory")

__device__ __forceinline__ void ldsm4(uint32_t* r, uint32_t addr) {
    asm volatile("ldmatrix.sync.aligned.m8n8.x4.shared.b16 {%0,%1,%2,%3}, [%4];"
                 : "=r"(r[0]), "=r"(r[1]), "=r"(r[2]), "=r"(r[3]) : "r"(addr));
}
__device__ __forceinline__ void mma16816(float* c, const uint32_t* a, const uint32_t* b) {
    asm volatile("mma.sync.aligned.m16n8k16.row.col.f32.f16.f16.f32 "
                 "{%0,%1,%2,%3}, {%4,%5,%6,%7}, {%8,%9}, {%0,%1,%2,%3};"
                 : "+f"(c[0]), "+f"(c[1]), "+f"(c[2]), "+f"(c[3])
                 : "r"(a[0]), "r"(a[1]), "r"(a[2]), "r"(a[3]), "r"(b[0]), "r"(b[1]));
}

// smem tile geometry: 128 rows x 64 fp16 (128B) padded to 144B (9*16B,
// conflict-free for ldmatrix)
#define ROWB        144
#define TILE_B      (128 * ROWB)      // 18432
#define STAGE_B     (2 * TILE_B)      // 36864 (A, B)
#define NSTAGE      3
#define SMEM_BYTES  (NSTAGE * STAGE_B)   // 110592 -> occ=1 (148 slots)

// ---------------------------------------------------------------------------
// Prep kernels (R14 layout): fused W/C transpose (blockIdx.z) + x convert.
// Also resets queue/counters/max for deterministic graph replay.
// ---------------------------------------------------------------------------
__global__ void transpose_half_kernel(const float* __restrict__ W,
                                      const float* __restrict__ C, int K)
{
    __shared__ float t[32][33];
    const int which = blockIdx.z;
    if (which == 0 && blockIdx.x == 0 && blockIdx.y == 0 &&
        threadIdx.x == 0 && threadIdx.y == 0) {
        g_max_bits = 0u;
        g_tix = 0u;
#pragma unroll
        for (int i = 0; i < 16; i++) g_colcnt[i] = 0u;
    }
    const float* src = which ? C : W;
    __half* dst = which ? g_Ct : g_Wt;
    const int kb = blockIdx.y * 32;
    const int mb = blockIdx.x * 32;
    const int tx = threadIdx.x, ty = threadIdx.y;
#pragma unroll
    for (int r = ty; r < 32; r += 8) {
        const int k = kb + r;
        t[r][tx] = (k < K) ? src[(size_t)k * LAT + mb + tx] : 0.f;
    }
    __syncthreads();
#pragma unroll
    for (int r = ty; r < 32; r += 8)
        dst[(size_t)(mb + r) * K1PAD + kb + tx] = __float2half_rn(t[tx][r]);
}

__global__ void x_half_kernel(const float* __restrict__ x, int n2)
{
    const int i = blockIdx.x * blockDim.x + threadIdx.x;
    if (i < n2) {
        const float2 v = ((const float2*)x)[i];
        ((__half2*)g_x)[i] = __floats2half2_rn(v.x, v.y);
    }
}

// ---------------------------------------------------------------------------
// GEMM mainloop (R14, unchanged except entry barrier): 128x128 CTA tile,
// 512 threads = 16 warps (4m x 4n, warp tile 32x32), K-chunks of 64,
// 3-stage cp.async pipeline. Entry __syncthreads() protects SMEM stage reuse
// across consecutive tiles in the persistent kernel.
// ---------------------------------------------------------------------------
__device__ __forceinline__ void gemm_main(
    const __half* __restrict__ A, const __half* __restrict__ B,
    int arow0, int brow0, int ldk, int nchunks,
    char* smem, float acc[2][4][4])
{
    const int tid = threadIdx.x;
    const int lane = tid & 31;
    const int w = tid >> 5;
    const int wm = w >> 2;
    const int wn = w & 3;
    const uint32_t sbase = smem_u32(smem);

    __syncthreads();   // previous tile's consumers must finish before reload

#pragma unroll
    for (int mt = 0; mt < 2; mt++)
#pragma unroll
        for (int nj = 0; nj < 4; nj++)
#pragma unroll
            for (int q = 0; q < 4; q++) acc[mt][nj][q] = 0.f;

    const int lr = tid >> 2;
    const int lcB = (tid & 3) * 32;
    const __half* gA = A + (size_t)(arow0 + lr) * ldk + (lcB >> 1);
    const __half* gB = B + (size_t)(brow0 + lr) * ldk + (lcB >> 1);
    const uint32_t adst = sbase + lr * ROWB + lcB;
    const uint32_t bdst = sbase + TILE_B + lr * ROWB + lcB;

    uint32_t aoff[4][2], boff[4][2];
#pragma unroll
    for (int ks = 0; ks < 4; ks++) {
#pragma unroll
        for (int mt = 0; mt < 2; mt++)
            aoff[ks][mt] = sbase + (uint32_t)((wm * 32 + mt * 16 + (lane & 15)) * ROWB
                                              + ks * 32 + (lane >> 4) * 16);
#pragma unroll
        for (int nt = 0; nt < 2; nt++)
            boff[ks][nt] = sbase + (uint32_t)(TILE_B
                              + (wn * 32 + nt * 16 + (lane & 7) + (lane >> 4) * 8) * ROWB
                              + ks * 32 + ((lane >> 3) & 1) * 16);
    }

#define LOAD_STAGE(c, s)                                                       \
    do {                                                                       \
        const char* pa = (const char*)(gA + (size_t)(c) * 64);                 \
        const char* pb = (const char*)(gB + (size_t)(c) * 64);                 \
        const uint32_t so_ = (uint32_t)(s) * STAGE_B;                          \
        cpasync16(adst + so_,      pa);   cpasync16(adst + so_ + 16, pa + 16); \
        cpasync16(bdst + so_,      pb);   cpasync16(bdst + so_ + 16, pb + 16); \
    } while (0)

    LOAD_STAGE(0, 0); CP_COMMIT();
    LOAD_STAGE(1, 1); CP_COMMIT();

    int s = 0, ps = 2;
    for (int c = 0; c < nchunks; ++c) {
        CP_WAIT1();
        __syncthreads();
        if (c + 2 < nchunks) LOAD_STAGE(c + 2, ps);
        CP_COMMIT();

        const uint32_t so = (uint32_t)s * STAGE_B;
        uint32_t a[4][2][4], b[4][2][4];
#pragma unroll
        for (int ks = 0; ks < 4; ks++) {
            ldsm4(a[ks][0], aoff[ks][0] + so);
            ldsm4(a[ks][1], aoff[ks][1] + so);
            ldsm4(b[ks][0], boff[ks][0] + so);
            ldsm4(b[ks][1], boff[ks][1] + so);
        }
#pragma unroll
        for (int ks = 0; ks < 4; ks++)
#pragma unroll
            for (int mt = 0; mt < 2; mt++)
#pragma unroll
                for (int nt = 0; nt < 2; nt++) {
                    mma16816(acc[mt][nt * 2 + 0], a[ks][mt], &b[ks][nt][0]);
                    mma16816(acc[mt][nt * 2 + 1], a[ks][mt], &b[ks][nt][2]);
                }
        if (++s == NSTAGE) s = 0;
        if (++ps == NSTAGE) ps = 0;
    }
#undef LOAD_STAGE
}

// ---------------------------------------------------------------------------
// Fused persistent GEMM kernel: 148 CTAs, dynamic tile queue.
//   entries 0..255   : gemm1 tiles, y = entry>>4 (n-block), x = entry&15 (m-blk)
//                      (column-major order: column y completes early)
//   entries 256..767 : gemm2 tiles, bx = (entry-256)>>5 (n-blk), by = &31 (b-blk)
//                      waits on g_colcnt[bx] == 16
// ---------------------------------------------------------------------------
#define N_T1 256u
#define N_TOT 768u
__global__ __launch_bounds__(512, 1) void gemm_fused(float* __restrict__ out)
{
    extern __shared__ __align__(128) char smem[];
    __shared__ float wmax[16];
    __shared__ unsigned s_t;
    const int tid = threadIdx.x;
    const int lane = tid & 31;
    const int w = tid >> 5;

    for (;;) {
        if (tid == 0) s_t = atomicAdd(&g_tix, 1u);
        __syncthreads();
        const unsigned t = s_t;
        if (t >= N_TOT) break;

        if (t < N_T1) {
            // ---- GEMM1 tile: Mt rows y*128.., cols x*128..
            const int y = (int)(t >> 4);
            const int x = (int)(t & 15u);
            float acc[2][4][4];
            gemm_main(g_Ct, g_Wt, y * 128, x * 128, K1PAD, K1PAD / 64, smem, acc);

            const int r0 = y * 128 + (w >> 2) * 32;
            const int c0 = x * 128 + (w & 3) * 32;
#pragma unroll
            for (int mt = 0; mt < 2; mt++) {
#pragma unroll
                for (int nj = 0; nj < 4; nj++) {
                    const int col = c0 + nj * 8 + (lane & 3) * 2;
                    const float* cc = acc[mt][nj];
#pragma unroll
                    for (int h = 0; h < 2; h++) {
                        const int r = r0 + mt * 16 + (lane >> 2) + h * 8;
                        *(__half2*)(g_Mt + (size_t)r * LAT + col) =
                            __floats2half2_rn(cc[2 * h + 0], cc[2 * h + 1]);
                    }
                }
            }
            __threadfence();
            __syncthreads();
            if (tid == 0) atomicAdd(&g_colcnt[y], 1u);
        } else {
            // ---- GEMM2 tile: out rows by*128.., cols bx*128..
            const unsigned u = t - N_T1;
            const int bx = (int)(u >> 5);
            const int by = (int)(u & 31u);
            if (tid == 0) {
                while (atomicAdd(&g_colcnt[bx], 0u) < 16u)
                    __nanosleep(64);
            }
            __syncthreads();

            float acc[2][4][4];
            gemm_main(g_x, g_Mt, by * 128, bx * 128, LAT, LAT / 64, smem, acc);

            const int r0 = by * 128 + (w >> 2) * 32;
            const int c0 = bx * 128 + (w & 3) * 32;
            float lmax = -3.402823466e+38f;
#pragma unroll
            for (int mt = 0; mt < 2; mt++) {
#pragma unroll
                for (int nj = 0; nj < 4; nj++) {
                    const int col = c0 + nj * 8 + (lane & 3) * 2;
                    const float* cc = acc[mt][nj];
#pragma unroll
                    for (int h = 0; h < 2; h++) {
                        const int r = r0 + mt * 16 + (lane >> 2) + h * 8;
                        float2 v = make_float2(cc[2 * h + 0], cc[2 * h + 1]);
                        lmax = fmaxf(lmax, fmaxf(v.x, v.y));
                        *(float2*)(out + (size_t)r * LAT + col) = v;
                    }
                }
            }
#pragma unroll
            for (int o = 16; o > 0; o >>= 1)
                lmax = fmaxf(lmax, __shfl_xor_sync(0xFFFFFFFFu, lmax, o));
            if (lane == 0) wmax[w] = lmax;
            __syncthreads();
            if (tid == 0) {
                float m = wmax[0];
#pragma unroll
                for (int i = 1; i < 16; i++) m = fmaxf(m, wmax[i]);
                atomicMax(&g_max_bits, fenc(m));
            }
        }
    }
}

// ---------------------------------------------------------------------------
// out *= 1/max
// ---------------------------------------------------------------------------
__global__ void scale_kernel(float* __restrict__ out, int n4)
{
    const float inv = 1.0f / fdec(g_max_bits);
    const int i = blockIdx.x * blockDim.x + threadIdx.x;
    if (i < n4) {
        float4 v = ((float4*)out)[i];
        v.x *= inv; v.y *= inv; v.z *= inv; v.w *= inv;
        ((float4*)out)[i] = v;
    }
}

// ---------------------------------------------------------------------------
extern "C" void kernel_launch(void* const* d_in, const int* in_sizes, int n_in,
                              void* d_out, int out_size)
{
    const float* x = (const float*)d_in[0];   // (B, 2048)
    const float* W = (const float*)d_in[1];   // (NF, 2048)
    const float* C = (const float*)d_in[2];   // (NF, 2048)
    float* out = (float*)d_out;

    const int B  = in_sizes[0] / LAT;         // 4096
    const int NF = in_sizes[1] / LAT;         // 2074
    (void)B;

    cudaFuncSetAttribute(gemm_fused, cudaFuncAttributeMaxDynamicSharedMemorySize,
                         SMEM_BYTES);

    dim3 tb(32, 8);
    transpose_half_kernel<<<dim3(LAT / 32, K1PAD / 32, 2), tb>>>(W, C, NF);
    const int n2 = MAXB * LAT / 2;
    x_half_kernel<<<(n2 + 255) / 256, 256>>>(x, n2);

    // fused persistent GEMM1+GEMM2 with dynamic queue (148 CTAs, occ=1)
    gemm_fused<<<148, 512, SMEM_BYTES>>>(out);

    const int n4 = out_size / 4;
    scale_kernel<<<(n4 + 255) / 256, 256>>>(out, n4);
}